// round 5
// baseline (speedup 1.0000x reference)
#include <cuda_runtime.h>
#include <cuda_bf16.h>
#include <math.h>

// Problem constants (fixed by the reference)
#define NMAX 50000
#define NEG_SLOPE 0.2f

// ---------------------------------------------------------------------------
// Scratch (static __device__ globals; runtime alloc is forbidden)
// ---------------------------------------------------------------------------
__device__ float4 g_h1[NMAX * 32];    // [N,128] layer-1 features (x @ W1)
__device__ float4 g_acc1[NMAX * 32];  // [N,128] unnormalized aggregation
__device__ float4 g_out1[NMAX * 32];  // [N,128] layer-1 output (post ELU)
__device__ float4 g_alS1[NMAX];       // [N,4] attention logits (src)
__device__ float4 g_alD1[NMAX];       // [N,4] attention logits (dst)
__device__ float4 g_s1[NMAX];         // [N,4] softmax denominators

__device__ float2 g_h2[NMAX * 32];    // [N,64] layer-2 features
__device__ float2 g_acc2[NMAX * 32];  // [N,64] unnormalized aggregation
__device__ float  g_alS2[NMAX];
__device__ float  g_alD2[NMAX];
__device__ float  g_s2[NMAX];

__device__ int    g_is64;             // edge_index dtype flag (1 = int64)

// ---------------------------------------------------------------------------
// Helpers
// ---------------------------------------------------------------------------
__device__ __forceinline__ float lrelu(float x) {
    return x > 0.f ? x : NEG_SLOPE * x;
}
__device__ __forceinline__ float comp4(float4 v, int i) {
    return i == 0 ? v.x : (i == 1 ? v.y : (i == 2 ? v.z : v.w));
}
__device__ __forceinline__ void red_add_v4(float4* p, float4 v) {
    asm volatile(
        "{\n\t.reg .u64 q;\n\t"
        "cvta.to.global.u64 q, %0;\n\t"
        "red.global.add.v4.f32 [q], {%1, %2, %3, %4};\n\t}"
        :: "l"(p), "f"(v.x), "f"(v.y), "f"(v.z), "f"(v.w) : "memory");
}
__device__ __forceinline__ void red_add_v2(float2* p, float2 v) {
    asm volatile(
        "{\n\t.reg .u64 q;\n\t"
        "cvta.to.global.u64 q, %0;\n\t"
        "red.global.add.v2.f32 [q], {%1, %2};\n\t}"
        :: "l"(p), "f"(v.x), "f"(v.y) : "memory");
}

// Load (src, dst) for edge e, dtype decided by is64 flag, clamped to [0, n).
__device__ __forceinline__ int2 load_edge(const void* ei, int E, int e,
                                          int is64, int n) {
    long long s, d;
    if (is64) {
        const long long* p = (const long long*)ei;
        s = p[e]; d = p[E + e];
    } else {
        const int* p = (const int*)ei;
        s = p[e]; d = p[E + e];
    }
    int si = (int)s, di = (int)d;
    si = min(max(si, 0), n - 1);
    di = min(max(di, 0), n - 1);
    return make_int2(si, di);
}

// ---------------------------------------------------------------------------
// Probe: decide whether edge_index is int64 or int32.
// If the buffer is int32, an int64 read has ~random high word -> out of range.
// ---------------------------------------------------------------------------
__global__ void probe_kernel(const void* ei, int n) {
    const long long* p = (const long long*)ei;
    bool ok = true;
    for (int i = 0; i < 256; i++) {
        long long v = p[i];
        if (v < 0 || v >= n) { ok = false; break; }
    }
    g_is64 = ok ? 1 : 0;
}

// ---------------------------------------------------------------------------
// GEMM: H[M, NC] = X[M, 128] @ W[128, NC]
// Block tile 64 x NC, 256 threads, each thread computes 4 rows x (NC/16) cols.
// ---------------------------------------------------------------------------
template <int LAYER>
__global__ __launch_bounds__(256) void gemm_kernel(const float* __restrict__ Xin,
                                                   const float* __restrict__ W,
                                                   int M) {
    constexpr int NC = (LAYER == 1) ? 128 : 64;
    constexpr int TN = NC / 16;
    const float* __restrict__ X = (LAYER == 1) ? Xin : (const float*)g_out1;
    float* __restrict__ H = (LAYER == 1) ? (float*)g_h1 : (float*)g_h2;

    __shared__ __align__(16) float Xs[64][32];
    __shared__ __align__(16) float Ws[32][NC];

    const int t = threadIdx.x;
    const int row0 = blockIdx.x * 64;
    const int tr = t >> 4;        // 0..15
    const int tc = t & 15;        // 0..15

    float acc[4][TN];
#pragma unroll
    for (int i = 0; i < 4; i++)
#pragma unroll
        for (int j = 0; j < TN; j++) acc[i][j] = 0.f;

    for (int kk = 0; kk < 128; kk += 32) {
#pragma unroll
        for (int i = 0; i < 8; i++) {
            int idx = i * 256 + t;
            int r = idx >> 5, c = idx & 31;
            int gr = row0 + r;
            Xs[r][c] = (gr < M) ? X[gr * 128 + kk + c] : 0.f;
        }
#pragma unroll
        for (int i = 0; i < NC / 8; i++) {
            int idx = i * 256 + t;
            int r = idx / NC, c = idx % NC;
            Ws[r][c] = W[(kk + r) * NC + c];
        }
        __syncthreads();

#pragma unroll
        for (int k = 0; k < 32; k++) {
            float xv[4];
#pragma unroll
            for (int i = 0; i < 4; i++) xv[i] = Xs[tr + 16 * i][k];
            float wv[TN];
            const float4* wrow = (const float4*)&Ws[k][0];
#pragma unroll
            for (int j4 = 0; j4 < TN / 4; j4++) {
                float4 w = wrow[tc * (TN / 4) + j4];
                wv[j4 * 4 + 0] = w.x; wv[j4 * 4 + 1] = w.y;
                wv[j4 * 4 + 2] = w.z; wv[j4 * 4 + 3] = w.w;
            }
#pragma unroll
            for (int i = 0; i < 4; i++)
#pragma unroll
                for (int j = 0; j < TN; j++) acc[i][j] += xv[i] * wv[j];
        }
        __syncthreads();
    }

#pragma unroll
    for (int i = 0; i < 4; i++) {
        int gr = row0 + tr + 16 * i;
        if (gr < M) {
#pragma unroll
            for (int j = 0; j < TN; j++) H[gr * NC + tc * TN + j] = acc[i][j];
        }
    }
}

// ---------------------------------------------------------------------------
// Logits layer 1: per-node attention logits over 4 heads x 32 ch.
// Also zeroes acc1 and s1 for the upcoming edge pass. Warp per node.
// ---------------------------------------------------------------------------
__global__ __launch_bounds__(256) void logits1_kernel(const float* __restrict__ aS,
                                                      const float* __restrict__ aD,
                                                      int n) {
    int gt = blockIdx.x * blockDim.x + threadIdx.x;
    int node = gt >> 5;
    int lane = gt & 31;
    if (node >= n) return;

    float4 h = g_h1[node * 32 + lane];
    float4 a = ((const float4*)aS)[lane];   // a_src1 is [4,32] = 32 float4
    float4 d = ((const float4*)aD)[lane];
    float ps = h.x * a.x + h.y * a.y + h.z * a.z + h.w * a.w;
    float pd = h.x * d.x + h.y * d.y + h.z * d.z + h.w * d.w;
    // reduce within each 8-lane head group
#pragma unroll
    for (int off = 4; off > 0; off >>= 1) {
        ps += __shfl_xor_sync(0xFFFFFFFF, ps, off);
        pd += __shfl_xor_sync(0xFFFFFFFF, pd, off);
    }
    int head = lane >> 3;
    if ((lane & 7) == 0) {
        ((float*)g_alS1)[node * 4 + head] = ps;
        ((float*)g_alD1)[node * 4 + head] = pd;
    }
    g_acc1[node * 32 + lane] = make_float4(0.f, 0.f, 0.f, 0.f);
    if (lane == 0) g_s1[node] = make_float4(0.f, 0.f, 0.f, 0.f);
}

// ---------------------------------------------------------------------------
// Logits layer 2: 1 head x 64 ch. Zeroes acc2/s2. Warp per node.
// ---------------------------------------------------------------------------
__global__ __launch_bounds__(256) void logits2_kernel(const float* __restrict__ aS,
                                                      const float* __restrict__ aD,
                                                      int n) {
    int gt = blockIdx.x * blockDim.x + threadIdx.x;
    int node = gt >> 5;
    int lane = gt & 31;
    if (node >= n) return;

    float2 h = g_h2[node * 32 + lane];
    float2 a = ((const float2*)aS)[lane];
    float2 d = ((const float2*)aD)[lane];
    float ps = h.x * a.x + h.y * a.y;
    float pd = h.x * d.x + h.y * d.y;
#pragma unroll
    for (int off = 16; off > 0; off >>= 1) {
        ps += __shfl_xor_sync(0xFFFFFFFF, ps, off);
        pd += __shfl_xor_sync(0xFFFFFFFF, pd, off);
    }
    if (lane == 0) {
        g_alS2[node] = ps;
        g_alD2[node] = pd;
        g_s2[node] = 0.f;
    }
    g_acc2[node * 32 + lane] = make_float2(0.f, 0.f);
}

// ---------------------------------------------------------------------------
// Edge pass layer 1: per edge, e_h = exp(lrelu(alS[src]+alD[dst])),
// acc1[dst] += e_h * h1[src], s1[dst] += e. Warp per 32-edge batch.
// ---------------------------------------------------------------------------
__global__ __launch_bounds__(256) void edge1_kernel(const void* __restrict__ ei,
                                                    int E, int n) {
    __shared__ int2 sd[8][32];
    __shared__ float4 se[8][32];

    int w = threadIdx.x >> 5;
    int lane = threadIdx.x & 31;
    int gw = blockIdx.x * 8 + w;
    int base = gw * 32;
    if (base >= E) return;
    int is64 = g_is64;

    int e = base + lane;
    int2 sdv = make_int2(0, 0);
    float4 ev = make_float4(0.f, 0.f, 0.f, 0.f);
    if (e < E) {
        sdv = load_edge(ei, E, e, is64, n);
        float4 as = g_alS1[sdv.x];
        float4 ad = g_alD1[sdv.y];
        ev.x = __expf(lrelu(as.x + ad.x));
        ev.y = __expf(lrelu(as.y + ad.y));
        ev.z = __expf(lrelu(as.z + ad.z));
        ev.w = __expf(lrelu(as.w + ad.w));
        red_add_v4(&g_s1[sdv.y], ev);   // all 4 head denominators in one red
    }
    sd[w][lane] = sdv;
    se[w][lane] = ev;
    __syncwarp();

    int cnt = min(32, E - base);
    int head = lane >> 3;
#pragma unroll 4
    for (int j = 0; j < cnt; j++) {
        int2 p = sd[w][j];      // broadcast
        float4 ee = se[w][j];   // broadcast
        float sc = comp4(ee, head);
        float4 v = g_h1[p.x * 32 + lane];
        float4 m = make_float4(v.x * sc, v.y * sc, v.z * sc, v.w * sc);
        red_add_v4(&g_acc1[p.y * 32 + lane], m);
    }
}

// ---------------------------------------------------------------------------
// Edge pass layer 2: 1 head, 64 ch. Lane covers a float2.
// ---------------------------------------------------------------------------
__global__ __launch_bounds__(256) void edge2_kernel(const void* __restrict__ ei,
                                                    int E, int n) {
    __shared__ int2 sd[8][32];
    __shared__ float se[8][32];

    int w = threadIdx.x >> 5;
    int lane = threadIdx.x & 31;
    int gw = blockIdx.x * 8 + w;
    int base = gw * 32;
    if (base >= E) return;
    int is64 = g_is64;

    int e = base + lane;
    int2 sdv = make_int2(0, 0);
    float ev = 0.f;
    if (e < E) {
        sdv = load_edge(ei, E, e, is64, n);
        ev = __expf(lrelu(g_alS2[sdv.x] + g_alD2[sdv.y]));
        atomicAdd(&g_s2[sdv.y], ev);
    }
    sd[w][lane] = sdv;
    se[w][lane] = ev;
    __syncwarp();

    int cnt = min(32, E - base);
#pragma unroll 4
    for (int j = 0; j < cnt; j++) {
        int2 p = sd[w][j];
        float ee = se[w][j];
        float2 v = g_h2[p.x * 32 + lane];
        float2 m = make_float2(v.x * ee, v.y * ee);
        red_add_v2(&g_acc2[p.y * 32 + lane], m);
    }
}

// ---------------------------------------------------------------------------
// Normalize layer 1: fold self-loop in, divide, add bias, ELU. Warp per node.
// ---------------------------------------------------------------------------
__global__ __launch_bounds__(256) void norm1_kernel(const float* __restrict__ b1,
                                                    int n) {
    int gt = blockIdx.x * blockDim.x + threadIdx.x;
    int node = gt >> 5;
    int lane = gt & 31;
    if (node >= n) return;

    int head = lane >> 3;
    float4 as = g_alS1[node];
    float4 ad = g_alD1[node];
    float4 tt = make_float4(as.x + ad.x, as.y + ad.y, as.z + ad.z, as.w + ad.w);
    float eh = __expf(lrelu(comp4(tt, head)));        // self-loop weight
    float denom = comp4(g_s1[node], head) + eh + 1e-16f;
    float inv = 1.f / denom;

    float4 a = g_acc1[node * 32 + lane];
    float4 hv = g_h1[node * 32 + lane];
    float4 bv = ((const float4*)b1)[lane];
    float4 o;
    o.x = (a.x + eh * hv.x) * inv + bv.x;
    o.y = (a.y + eh * hv.y) * inv + bv.y;
    o.z = (a.z + eh * hv.z) * inv + bv.z;
    o.w = (a.w + eh * hv.w) * inv + bv.w;
    // ELU
    o.x = o.x > 0.f ? o.x : expm1f(o.x);
    o.y = o.y > 0.f ? o.y : expm1f(o.y);
    o.z = o.z > 0.f ? o.z : expm1f(o.z);
    o.w = o.w > 0.f ? o.w : expm1f(o.w);
    g_out1[node * 32 + lane] = o;
}

// ---------------------------------------------------------------------------
// Normalize layer 2: fold self-loop, divide, add bias, write d_out.
// ---------------------------------------------------------------------------
__global__ __launch_bounds__(256) void norm2_kernel(const float* __restrict__ b2,
                                                    float* __restrict__ out,
                                                    int n) {
    int gt = blockIdx.x * blockDim.x + threadIdx.x;
    int node = gt >> 5;
    int lane = gt & 31;
    if (node >= n) return;

    float eh = __expf(lrelu(g_alS2[node] + g_alD2[node]));
    float inv = 1.f / (g_s2[node] + eh + 1e-16f);

    float2 a = g_acc2[node * 32 + lane];
    float2 hv = g_h2[node * 32 + lane];
    float2 bv = ((const float2*)b2)[lane];
    float2 o;
    o.x = (a.x + eh * hv.x) * inv + bv.x;
    o.y = (a.y + eh * hv.y) * inv + bv.y;
    ((float2*)out)[node * 32 + lane] = o;
}

// ---------------------------------------------------------------------------
// Launch
// ---------------------------------------------------------------------------
extern "C" void kernel_launch(void* const* d_in, const int* in_sizes, int n_in,
                              void* d_out, int out_size) {
    const float* x   = (const float*)d_in[0];
    const void*  ei  = d_in[1];
    const float* W1  = (const float*)d_in[2];
    const float* aS1 = (const float*)d_in[3];
    const float* aD1 = (const float*)d_in[4];
    const float* b1  = (const float*)d_in[5];
    const float* W2  = (const float*)d_in[6];
    const float* aS2 = (const float*)d_in[7];
    const float* aD2 = (const float*)d_in[8];
    const float* b2  = (const float*)d_in[9];
    float* out       = (float*)d_out;

    const int n = in_sizes[0] / 128;
    const int E = in_sizes[1] / 2;

    const int gemm_blocks = (n + 63) / 64;
    const int node_blocks = (n + 7) / 8;                 // warp per node
    const int edge_blocks = ((E + 31) / 32 + 7) / 8;     // warp per 32-edge batch

    probe_kernel<<<1, 1>>>(ei, n);

    // Layer 1
    gemm_kernel<1><<<gemm_blocks, 256>>>(x, W1, n);
    logits1_kernel<<<node_blocks, 256>>>(aS1, aD1, n);
    edge1_kernel<<<edge_blocks, 256>>>(ei, E, n);
    norm1_kernel<<<node_blocks, 256>>>(b1, n);

    // Layer 2
    gemm_kernel<2><<<gemm_blocks, 256>>>(nullptr, W2, n);
    logits2_kernel<<<node_blocks, 256>>>(aS2, aD2, n);
    edge2_kernel<<<edge_blocks, 256>>>(ei, E, n);
    norm2_kernel<<<node_blocks, 256>>>(b2, out, n);
}

// round 6
// speedup vs baseline: 1.1157x; 1.1157x over previous
#include <cuda_runtime.h>
#include <cuda_bf16.h>
#include <math.h>

// Problem constants (fixed by the reference)
#define NMAX 50000
#define EMAX 1600000
#define NEG_SLOPE 0.2f

// ---------------------------------------------------------------------------
// Scratch (static __device__ globals; runtime alloc is forbidden)
// ---------------------------------------------------------------------------
__device__ float4 g_h1[NMAX * 32];    // [N,128] layer-1 features (x @ W1)
__device__ float4 g_out1[NMAX * 32];  // [N,128] layer-1 output (post ELU)
__device__ float4 g_alS1[NMAX];       // [N,4] attention logits (src)
__device__ float4 g_alD1[NMAX];       // [N,4] attention logits (dst)

__device__ float2 g_h2[NMAX * 32];    // [N,64] layer-2 features
__device__ float  g_alS2[NMAX];
__device__ float  g_alD2[NMAX];

__device__ int    g_is64;             // edge_index dtype flag (1 = int64)
__device__ int    g_deg[NMAX];        // dst-degree histogram
__device__ int    g_row[NMAX + 1];    // CSR row offsets (by dst)
__device__ int    g_cursor[NMAX];     // scatter cursors
__device__ int    g_esrc[EMAX];       // src ids sorted by dst

// ---------------------------------------------------------------------------
// Helpers
// ---------------------------------------------------------------------------
__device__ __forceinline__ float lrelu(float x) {
    return x > 0.f ? x : NEG_SLOPE * x;
}
__device__ __forceinline__ float comp4(float4 v, int i) {
    return i == 0 ? v.x : (i == 1 ? v.y : (i == 2 ? v.z : v.w));
}

// ---------------------------------------------------------------------------
// Probe: decide whether edge_index is int64 or int32.
// ---------------------------------------------------------------------------
__global__ void probe_kernel(const void* ei, int n) {
    const long long* p = (const long long*)ei;
    bool ok = true;
    for (int i = 0; i < 256; i++) {
        long long v = p[i];
        if (v < 0 || v >= n) { ok = false; break; }
    }
    g_is64 = ok ? 1 : 0;
}

// ---------------------------------------------------------------------------
// CSR build: zero -> histogram -> scan -> permute
// ---------------------------------------------------------------------------
__global__ void zero_deg_kernel(int n) {
    int i = blockIdx.x * blockDim.x + threadIdx.x;
    if (i < n) g_deg[i] = 0;
}

__global__ void hist_kernel(const void* __restrict__ ei, int E, int n) {
    int e = blockIdx.x * blockDim.x + threadIdx.x;
    if (e >= E) return;
    int d;
    if (g_is64) d = (int)((const long long*)ei)[E + e];
    else        d = ((const int*)ei)[E + e];
    d = min(max(d, 0), n - 1);
    atomicAdd(&g_deg[d], 1);
}

__global__ __launch_bounds__(1024) void scan_kernel(int n) {
    __shared__ int part[1024];
    int t = threadIdx.x;
    int chunk = (n + 1023) >> 10;
    int start = min(t * chunk, n);
    int end = min(start + chunk, n);
    int s = 0;
    for (int i = start; i < end; i++) s += g_deg[i];
    part[t] = s;
    __syncthreads();
    for (int off = 1; off < 1024; off <<= 1) {
        int v = (t >= off) ? part[t - off] : 0;
        __syncthreads();
        part[t] += v;
        __syncthreads();
    }
    int base = (t == 0) ? 0 : part[t - 1];
    for (int i = start; i < end; i++) {
        int dg = g_deg[i];
        g_row[i] = base;
        g_cursor[i] = base;
        base += dg;
    }
    if (end == n && start < n) g_row[n] = base;
}

__global__ void permute_kernel(const void* __restrict__ ei, int E, int n) {
    int e = blockIdx.x * blockDim.x + threadIdx.x;
    if (e >= E) return;
    int s, d;
    if (g_is64) {
        s = (int)((const long long*)ei)[e];
        d = (int)((const long long*)ei)[E + e];
    } else {
        s = ((const int*)ei)[e];
        d = ((const int*)ei)[E + e];
    }
    s = min(max(s, 0), n - 1);
    d = min(max(d, 0), n - 1);
    int pos = atomicAdd(&g_cursor[d], 1);
    if (pos < EMAX) g_esrc[pos] = s;
}

// ---------------------------------------------------------------------------
// GEMM with fused attention-logit epilogue.
// H[M, NC] = X[M, 128] @ W[128, NC]; then alS/alD per node computed in-regs.
// Block tile 64 x NC, 256 threads; thread (tr, tc) owns rows tr+16i,
// cols tc*TN..tc*TN+TN-1 (complete rows per block -> logits reducible).
// ---------------------------------------------------------------------------
template <int LAYER>
__global__ __launch_bounds__(256) void gemm_kernel(const float* __restrict__ Xin,
                                                   const float* __restrict__ W,
                                                   const float* __restrict__ aS,
                                                   const float* __restrict__ aD,
                                                   int M) {
    constexpr int NC = (LAYER == 1) ? 128 : 64;
    constexpr int TN = NC / 16;
    const float* __restrict__ X = (LAYER == 1) ? Xin : (const float*)g_out1;
    float* __restrict__ H = (LAYER == 1) ? (float*)g_h1 : (float*)g_h2;

    __shared__ __align__(16) float Xs[64][32];
    __shared__ __align__(16) float Ws[32][NC];

    const int t = threadIdx.x;
    const int row0 = blockIdx.x * 64;
    const int tr = t >> 4;        // 0..15
    const int tc = t & 15;        // 0..15

    float acc[4][TN];
#pragma unroll
    for (int i = 0; i < 4; i++)
#pragma unroll
        for (int j = 0; j < TN; j++) acc[i][j] = 0.f;

    for (int kk = 0; kk < 128; kk += 32) {
#pragma unroll
        for (int i = 0; i < 8; i++) {
            int idx = i * 256 + t;
            int r = idx >> 5, c = idx & 31;
            int gr = row0 + r;
            Xs[r][c] = (gr < M) ? X[gr * 128 + kk + c] : 0.f;
        }
#pragma unroll
        for (int i = 0; i < NC / 8; i++) {
            int idx = i * 256 + t;
            int r = idx / NC, c = idx % NC;
            Ws[r][c] = W[(kk + r) * NC + c];
        }
        __syncthreads();

#pragma unroll
        for (int k = 0; k < 32; k++) {
            float xv[4];
#pragma unroll
            for (int i = 0; i < 4; i++) xv[i] = Xs[tr + 16 * i][k];
            float wv[TN];
            const float4* wrow = (const float4*)&Ws[k][0];
#pragma unroll
            for (int j4 = 0; j4 < TN / 4; j4++) {
                float4 w = wrow[tc * (TN / 4) + j4];
                wv[j4 * 4 + 0] = w.x; wv[j4 * 4 + 1] = w.y;
                wv[j4 * 4 + 2] = w.z; wv[j4 * 4 + 3] = w.w;
            }
#pragma unroll
            for (int i = 0; i < 4; i++)
#pragma unroll
                for (int j = 0; j < TN; j++) acc[i][j] += xv[i] * wv[j];
        }
        __syncthreads();
    }

    // Store H
#pragma unroll
    for (int i = 0; i < 4; i++) {
        int gr = row0 + tr + 16 * i;
        if (gr < M) {
#pragma unroll
            for (int j = 0; j < TN; j++) H[gr * NC + tc * TN + j] = acc[i][j];
        }
    }

    // Fused logits
    if (LAYER == 1) {
        // head = tc>>2, sub = tc&3; cols = head*32 + sub*8 + j
        int head = tc >> 2;
        int sub = tc & 3;
        float av[8], dv[8];
#pragma unroll
        for (int j = 0; j < 8; j++) {
            av[j] = aS[head * 32 + sub * 8 + j];
            dv[j] = aD[head * 32 + sub * 8 + j];
        }
#pragma unroll
        for (int i = 0; i < 4; i++) {
            float ps = 0.f, pd = 0.f;
#pragma unroll
            for (int j = 0; j < 8; j++) {
                ps += acc[i][j] * av[j];
                pd += acc[i][j] * dv[j];
            }
            // reduce across the 4 sub lanes (contiguous lane ids)
            ps += __shfl_xor_sync(0xFFFFFFFF, ps, 1);
            ps += __shfl_xor_sync(0xFFFFFFFF, ps, 2);
            pd += __shfl_xor_sync(0xFFFFFFFF, pd, 1);
            pd += __shfl_xor_sync(0xFFFFFFFF, pd, 2);
            int gr = row0 + tr + 16 * i;
            if (sub == 0 && gr < M) {
                ((float*)g_alS1)[gr * 4 + head] = ps;
                ((float*)g_alD1)[gr * 4 + head] = pd;
            }
        }
    } else {
        // 1 head over 64 cols; cols = tc*4 + j; reduce across all 16 tc lanes
        float av[4], dv[4];
#pragma unroll
        for (int j = 0; j < 4; j++) {
            av[j] = aS[tc * 4 + j];
            dv[j] = aD[tc * 4 + j];
        }
#pragma unroll
        for (int i = 0; i < 4; i++) {
            float ps = 0.f, pd = 0.f;
#pragma unroll
            for (int j = 0; j < 4; j++) {
                ps += acc[i][j] * av[j];
                pd += acc[i][j] * dv[j];
            }
#pragma unroll
            for (int off = 1; off < 16; off <<= 1) {
                ps += __shfl_xor_sync(0xFFFFFFFF, ps, off);
                pd += __shfl_xor_sync(0xFFFFFFFF, pd, off);
            }
            int gr = row0 + tr + 16 * i;
            if (tc == 0 && gr < M) {
                g_alS2[gr] = ps;
                g_alD2[gr] = pd;
            }
        }
    }
}

// ---------------------------------------------------------------------------
// Fused GAT layer 1: warp per dst node. Walk CSR row, gather h1[src],
// accumulate numerator/denominator in registers, fold self-loop,
// normalize, add bias, ELU, write g_out1. No atomics.
// ---------------------------------------------------------------------------
__global__ __launch_bounds__(256) void gat1_kernel(const float* __restrict__ b1,
                                                   int n) {
    __shared__ int ssrc[8][32];
    __shared__ float4 sev[8][32];

    int w = threadIdx.x >> 5;
    int lane = threadIdx.x & 31;
    int node = blockIdx.x * 8 + w;
    if (node >= n) return;
    int head = lane >> 3;

    int r0 = g_row[node];
    int r1 = g_row[node + 1];
    float4 ad = g_alD1[node];

    float4 accv = make_float4(0.f, 0.f, 0.f, 0.f);
    float4 den = make_float4(0.f, 0.f, 0.f, 0.f);

    for (int base = r0; base < r1; base += 32) {
        int e = base + lane;
        int s = 0;
        float4 ev = make_float4(0.f, 0.f, 0.f, 0.f);
        if (e < r1) {
            s = g_esrc[e];
            float4 as = g_alS1[s];
            ev.x = __expf(lrelu(as.x + ad.x));
            ev.y = __expf(lrelu(as.y + ad.y));
            ev.z = __expf(lrelu(as.z + ad.z));
            ev.w = __expf(lrelu(as.w + ad.w));
            den.x += ev.x; den.y += ev.y; den.z += ev.z; den.w += ev.w;
        }
        ssrc[w][lane] = s;
        sev[w][lane] = ev;
        __syncwarp();

        int cnt = min(32, r1 - base);
#pragma unroll 4
        for (int j = 0; j < cnt; j++) {
            int sj = ssrc[w][j];                           // smem broadcast
            float sc = ((const float*)(sev[w] + j))[head]; // conflict-free
            float4 v = g_h1[sj * 32 + lane];
            accv.x += v.x * sc;
            accv.y += v.y * sc;
            accv.z += v.z * sc;
            accv.w += v.w * sc;
        }
        __syncwarp();
    }

    // Reduce denominators across the warp (per-head sums)
#pragma unroll
    for (int off = 16; off > 0; off >>= 1) {
        den.x += __shfl_xor_sync(0xFFFFFFFF, den.x, off);
        den.y += __shfl_xor_sync(0xFFFFFFFF, den.y, off);
        den.z += __shfl_xor_sync(0xFFFFFFFF, den.z, off);
        den.w += __shfl_xor_sync(0xFFFFFFFF, den.w, off);
    }

    // Self-loop (appended edge node->node)
    float4 asn = g_alS1[node];
    float4 evs;
    evs.x = __expf(lrelu(asn.x + ad.x));
    evs.y = __expf(lrelu(asn.y + ad.y));
    evs.z = __expf(lrelu(asn.z + ad.z));
    evs.w = __expf(lrelu(asn.w + ad.w));
    float eh = comp4(evs, head);
    float4 hv = g_h1[node * 32 + lane];
    accv.x += eh * hv.x;
    accv.y += eh * hv.y;
    accv.z += eh * hv.z;
    accv.w += eh * hv.w;

    float inv = 1.f / (comp4(den, head) + eh + 1e-16f);
    float4 bv = ((const float4*)b1)[lane];
    float4 o;
    o.x = accv.x * inv + bv.x;
    o.y = accv.y * inv + bv.y;
    o.z = accv.z * inv + bv.z;
    o.w = accv.w * inv + bv.w;
    // ELU
    o.x = o.x > 0.f ? o.x : expm1f(o.x);
    o.y = o.y > 0.f ? o.y : expm1f(o.y);
    o.z = o.z > 0.f ? o.z : expm1f(o.z);
    o.w = o.w > 0.f ? o.w : expm1f(o.w);
    g_out1[node * 32 + lane] = o;
}

// ---------------------------------------------------------------------------
// Fused GAT layer 2: warp per dst node, 1 head, 64 ch. Writes d_out.
// ---------------------------------------------------------------------------
__global__ __launch_bounds__(256) void gat2_kernel(const float* __restrict__ b2,
                                                   float* __restrict__ out,
                                                   int n) {
    __shared__ int ssrc[8][32];
    __shared__ float sev[8][32];

    int w = threadIdx.x >> 5;
    int lane = threadIdx.x & 31;
    int node = blockIdx.x * 8 + w;
    if (node >= n) return;

    int r0 = g_row[node];
    int r1 = g_row[node + 1];
    float ad = g_alD2[node];

    float2 accv = make_float2(0.f, 0.f);
    float den = 0.f;

    for (int base = r0; base < r1; base += 32) {
        int e = base + lane;
        int s = 0;
        float ev = 0.f;
        if (e < r1) {
            s = g_esrc[e];
            ev = __expf(lrelu(g_alS2[s] + ad));
            den += ev;
        }
        ssrc[w][lane] = s;
        sev[w][lane] = ev;
        __syncwarp();

        int cnt = min(32, r1 - base);
#pragma unroll 4
        for (int j = 0; j < cnt; j++) {
            int sj = ssrc[w][j];
            float ee = sev[w][j];
            float2 v = g_h2[sj * 32 + lane];
            accv.x += v.x * ee;
            accv.y += v.y * ee;
        }
        __syncwarp();
    }

#pragma unroll
    for (int off = 16; off > 0; off >>= 1)
        den += __shfl_xor_sync(0xFFFFFFFF, den, off);

    // Self-loop
    float eh = __expf(lrelu(g_alS2[node] + ad));
    float2 hv = g_h2[node * 32 + lane];
    accv.x += eh * hv.x;
    accv.y += eh * hv.y;

    float inv = 1.f / (den + eh + 1e-16f);
    float2 bv = ((const float2*)b2)[lane];
    float2 o;
    o.x = accv.x * inv + bv.x;
    o.y = accv.y * inv + bv.y;
    ((float2*)out)[node * 32 + lane] = o;
}

// ---------------------------------------------------------------------------
// Launch
// ---------------------------------------------------------------------------
extern "C" void kernel_launch(void* const* d_in, const int* in_sizes, int n_in,
                              void* d_out, int out_size) {
    const float* x   = (const float*)d_in[0];
    const void*  ei  = d_in[1];
    const float* W1  = (const float*)d_in[2];
    const float* aS1 = (const float*)d_in[3];
    const float* aD1 = (const float*)d_in[4];
    const float* b1  = (const float*)d_in[5];
    const float* W2  = (const float*)d_in[6];
    const float* aS2 = (const float*)d_in[7];
    const float* aD2 = (const float*)d_in[8];
    const float* b2  = (const float*)d_in[9];
    float* out       = (float*)d_out;

    const int n = in_sizes[0] / 128;
    const int E = in_sizes[1] / 2;

    const int gemm_blocks = (n + 63) / 64;
    const int node_blocks = (n + 7) / 8;        // warp per node
    const int edge_blocks = (E + 255) / 256;

    // Edge dtype probe + CSR build (shared by both layers)
    probe_kernel<<<1, 1>>>(ei, n);
    zero_deg_kernel<<<(n + 255) / 256, 256>>>(n);
    hist_kernel<<<edge_blocks, 256>>>(ei, E, n);
    scan_kernel<<<1, 1024>>>(n);
    permute_kernel<<<edge_blocks, 256>>>(ei, E, n);

    // Layer 1
    gemm_kernel<1><<<gemm_blocks, 256>>>(x, W1, aS1, aD1, n);
    gat1_kernel<<<node_blocks, 256>>>(b1, n);

    // Layer 2
    gemm_kernel<2><<<gemm_blocks, 256>>>(nullptr, W2, aS2, aD2, n);
    gat2_kernel<<<node_blocks, 256>>>(b2, out, n);
}

// round 7
// speedup vs baseline: 1.4631x; 1.3114x over previous
#include <cuda_runtime.h>
#include <cuda_bf16.h>
#include <math.h>

// Problem constants (fixed by the reference)
#define NMAX 50000
#define EMAX 1600000
#define NEG_SLOPE 0.2f

#define SCAN_T 256
#define SCAN_I 8
#define SCAN_CHUNK (SCAN_T * SCAN_I)   // 2048 elements per block
#define SCAN_MAXB ((NMAX + SCAN_CHUNK - 1) / SCAN_CHUNK + 1)

// ---------------------------------------------------------------------------
// Scratch (static __device__ globals; runtime alloc is forbidden)
// ---------------------------------------------------------------------------
__device__ float4 g_h1[NMAX * 32];    // [N,128] layer-1 features (x @ W1)
__device__ float4 g_out1[NMAX * 32];  // [N,128] layer-1 output (post ELU)
__device__ float4 g_alS1[NMAX];       // [N,4] attention logits (src)
__device__ float4 g_alD1[NMAX];       // [N,4] attention logits (dst)

__device__ float2 g_h2[NMAX * 32];    // [N,64] layer-2 features
__device__ float  g_alS2[NMAX];
__device__ float  g_alD2[NMAX];

__device__ int    g_is64;             // edge_index dtype flag (1 = int64)
__device__ int    g_deg[NMAX];        // dst-degree histogram
__device__ int    g_row[NMAX + 1];    // CSR row offsets (by dst)
__device__ int    g_cursor[NMAX];     // scatter cursors
__device__ int    g_esrc[EMAX];       // src ids sorted by dst
__device__ int    g_bsum[SCAN_MAXB];  // per-block degree sums
__device__ int    g_boff[SCAN_MAXB];  // per-block exclusive offsets

// ---------------------------------------------------------------------------
// Helpers
// ---------------------------------------------------------------------------
__device__ __forceinline__ float lrelu(float x) {
    return x > 0.f ? x : NEG_SLOPE * x;
}
__device__ __forceinline__ float comp4(float4 v, int i) {
    return i == 0 ? v.x : (i == 1 ? v.y : (i == 2 ? v.z : v.w));
}

// ---------------------------------------------------------------------------
// Probe (parallel): decide whether edge_index is int64 or int32.
// 256 threads each validate one int64-interpreted entry.
// ---------------------------------------------------------------------------
__global__ void probe_kernel(const void* ei, int n) {
    __shared__ int bad;
    if (threadIdx.x == 0) bad = 0;
    __syncthreads();
    const long long* p = (const long long*)ei;
    long long v = p[threadIdx.x];
    if (v < 0 || v >= n) atomicOr(&bad, 1);
    __syncthreads();
    if (threadIdx.x == 0) g_is64 = bad ? 0 : 1;
}

// ---------------------------------------------------------------------------
// CSR build: zero -> histogram -> 3-phase scan -> permute
// ---------------------------------------------------------------------------
__global__ void zero_deg_kernel(int n) {
    int i = blockIdx.x * blockDim.x + threadIdx.x;
    if (i < n) g_deg[i] = 0;
}

__global__ void hist_kernel(const void* __restrict__ ei, int E, int n) {
    int e = blockIdx.x * blockDim.x + threadIdx.x;
    if (e >= E) return;
    int d;
    if (g_is64) d = (int)((const long long*)ei)[E + e];
    else        d = ((const int*)ei)[E + e];
    d = min(max(d, 0), n - 1);
    atomicAdd(&g_deg[d], 1);
}

// Phase A: per-block sum of 2048 degrees.
__global__ __launch_bounds__(SCAN_T) void scanA_kernel(int n) {
    __shared__ int sm[SCAN_T];
    int t = threadIdx.x;
    int base = blockIdx.x * SCAN_CHUNK + t * SCAN_I;
    int s = 0;
#pragma unroll
    for (int i = 0; i < SCAN_I; i++) {
        int idx = base + i;
        if (idx < n) s += g_deg[idx];
    }
    sm[t] = s;
    __syncthreads();
#pragma unroll
    for (int off = SCAN_T / 2; off > 0; off >>= 1) {
        if (t < off) sm[t] += sm[t + off];
        __syncthreads();
    }
    if (t == 0) g_bsum[blockIdx.x] = sm[0];
}

// Phase B: serial exclusive scan over <=25 block sums (tiny).
__global__ void scanB_kernel(int nb, int n) {
    if (threadIdx.x != 0) return;
    int acc = 0;
    for (int i = 0; i < nb; i++) {
        g_boff[i] = acc;
        acc += g_bsum[i];
    }
    g_row[n] = acc;
}

// Phase C: per-block exclusive scan with global offset; writes row + cursor.
__global__ __launch_bounds__(SCAN_T) void scanC_kernel(int n) {
    __shared__ int sm[SCAN_T];
    int t = threadIdx.x;
    int base = blockIdx.x * SCAN_CHUNK + t * SCAN_I;
    int loc[SCAN_I];
    int s = 0;
#pragma unroll
    for (int i = 0; i < SCAN_I; i++) {
        int idx = base + i;
        loc[i] = (idx < n) ? g_deg[idx] : 0;
        s += loc[i];
    }
    sm[t] = s;
    __syncthreads();
    // inclusive Hillis-Steele over thread totals
#pragma unroll
    for (int off = 1; off < SCAN_T; off <<= 1) {
        int v = (t >= off) ? sm[t - off] : 0;
        __syncthreads();
        sm[t] += v;
        __syncthreads();
    }
    int acc = ((t == 0) ? 0 : sm[t - 1]) + g_boff[blockIdx.x];
#pragma unroll
    for (int i = 0; i < SCAN_I; i++) {
        int idx = base + i;
        if (idx < n) {
            g_row[idx] = acc;
            g_cursor[idx] = acc;
            acc += loc[i];
        }
    }
}

__global__ void permute_kernel(const void* __restrict__ ei, int E, int n) {
    int e = blockIdx.x * blockDim.x + threadIdx.x;
    if (e >= E) return;
    int s, d;
    if (g_is64) {
        s = (int)((const long long*)ei)[e];
        d = (int)((const long long*)ei)[E + e];
    } else {
        s = ((const int*)ei)[e];
        d = ((const int*)ei)[E + e];
    }
    s = min(max(s, 0), n - 1);
    d = min(max(d, 0), n - 1);
    int pos = atomicAdd(&g_cursor[d], 1);
    if (pos < EMAX) g_esrc[pos] = s;
}

// ---------------------------------------------------------------------------
// GEMM with fused attention-logit epilogue.
// H[M, NC] = X[M, 128] @ W[128, NC]; then alS/alD per node computed in-regs.
// ---------------------------------------------------------------------------
template <int LAYER>
__global__ __launch_bounds__(256) void gemm_kernel(const float* __restrict__ Xin,
                                                   const float* __restrict__ W,
                                                   const float* __restrict__ aS,
                                                   const float* __restrict__ aD,
                                                   int M) {
    constexpr int NC = (LAYER == 1) ? 128 : 64;
    constexpr int TN = NC / 16;
    const float* __restrict__ X = (LAYER == 1) ? Xin : (const float*)g_out1;
    float* __restrict__ H = (LAYER == 1) ? (float*)g_h1 : (float*)g_h2;

    __shared__ __align__(16) float Xs[64][32];
    __shared__ __align__(16) float Ws[32][NC];

    const int t = threadIdx.x;
    const int row0 = blockIdx.x * 64;
    const int tr = t >> 4;        // 0..15
    const int tc = t & 15;        // 0..15

    float acc[4][TN];
#pragma unroll
    for (int i = 0; i < 4; i++)
#pragma unroll
        for (int j = 0; j < TN; j++) acc[i][j] = 0.f;

    for (int kk = 0; kk < 128; kk += 32) {
#pragma unroll
        for (int i = 0; i < 8; i++) {
            int idx = i * 256 + t;
            int r = idx >> 5, c = idx & 31;
            int gr = row0 + r;
            Xs[r][c] = (gr < M) ? X[gr * 128 + kk + c] : 0.f;
        }
#pragma unroll
        for (int i = 0; i < NC / 8; i++) {
            int idx = i * 256 + t;
            int r = idx / NC, c = idx % NC;
            Ws[r][c] = W[(kk + r) * NC + c];
        }
        __syncthreads();

#pragma unroll
        for (int k = 0; k < 32; k++) {
            float xv[4];
#pragma unroll
            for (int i = 0; i < 4; i++) xv[i] = Xs[tr + 16 * i][k];
            float wv[TN];
            const float4* wrow = (const float4*)&Ws[k][0];
#pragma unroll
            for (int j4 = 0; j4 < TN / 4; j4++) {
                float4 w = wrow[tc * (TN / 4) + j4];
                wv[j4 * 4 + 0] = w.x; wv[j4 * 4 + 1] = w.y;
                wv[j4 * 4 + 2] = w.z; wv[j4 * 4 + 3] = w.w;
            }
#pragma unroll
            for (int i = 0; i < 4; i++)
#pragma unroll
                for (int j = 0; j < TN; j++) acc[i][j] += xv[i] * wv[j];
        }
        __syncthreads();
    }

    // Store H
#pragma unroll
    for (int i = 0; i < 4; i++) {
        int gr = row0 + tr + 16 * i;
        if (gr < M) {
#pragma unroll
            for (int j = 0; j < TN; j++) H[gr * NC + tc * TN + j] = acc[i][j];
        }
    }

    // Fused logits
    if (LAYER == 1) {
        int head = tc >> 2;
        int sub = tc & 3;
        float av[8], dv[8];
#pragma unroll
        for (int j = 0; j < 8; j++) {
            av[j] = aS[head * 32 + sub * 8 + j];
            dv[j] = aD[head * 32 + sub * 8 + j];
        }
#pragma unroll
        for (int i = 0; i < 4; i++) {
            float ps = 0.f, pd = 0.f;
#pragma unroll
            for (int j = 0; j < 8; j++) {
                ps += acc[i][j] * av[j];
                pd += acc[i][j] * dv[j];
            }
            ps += __shfl_xor_sync(0xFFFFFFFF, ps, 1);
            ps += __shfl_xor_sync(0xFFFFFFFF, ps, 2);
            pd += __shfl_xor_sync(0xFFFFFFFF, pd, 1);
            pd += __shfl_xor_sync(0xFFFFFFFF, pd, 2);
            int gr = row0 + tr + 16 * i;
            if (sub == 0 && gr < M) {
                ((float*)g_alS1)[gr * 4 + head] = ps;
                ((float*)g_alD1)[gr * 4 + head] = pd;
            }
        }
    } else {
        float av[4], dv[4];
#pragma unroll
        for (int j = 0; j < 4; j++) {
            av[j] = aS[tc * 4 + j];
            dv[j] = aD[tc * 4 + j];
        }
#pragma unroll
        for (int i = 0; i < 4; i++) {
            float ps = 0.f, pd = 0.f;
#pragma unroll
            for (int j = 0; j < 4; j++) {
                ps += acc[i][j] * av[j];
                pd += acc[i][j] * dv[j];
            }
#pragma unroll
            for (int off = 1; off < 16; off <<= 1) {
                ps += __shfl_xor_sync(0xFFFFFFFF, ps, off);
                pd += __shfl_xor_sync(0xFFFFFFFF, pd, off);
            }
            int gr = row0 + tr + 16 * i;
            if (tc == 0 && gr < M) {
                g_alS2[gr] = ps;
                g_alD2[gr] = pd;
            }
        }
    }
}

// ---------------------------------------------------------------------------
// Fused GAT layer 1: warp per dst node. Walk CSR row, gather h1[src],
// accumulate numerator/denominator in registers, fold self-loop,
// normalize, add bias, ELU, write g_out1. No atomics.
// ---------------------------------------------------------------------------
__global__ __launch_bounds__(256) void gat1_kernel(const float* __restrict__ b1,
                                                   int n) {
    __shared__ int ssrc[8][32];
    __shared__ float4 sev[8][32];

    int w = threadIdx.x >> 5;
    int lane = threadIdx.x & 31;
    int node = blockIdx.x * 8 + w;
    if (node >= n) return;
    int head = lane >> 3;

    int r0 = g_row[node];
    int r1 = g_row[node + 1];
    float4 ad = g_alD1[node];

    float4 accv = make_float4(0.f, 0.f, 0.f, 0.f);
    float4 den = make_float4(0.f, 0.f, 0.f, 0.f);

    for (int base = r0; base < r1; base += 32) {
        int e = base + lane;
        int s = 0;
        float4 ev = make_float4(0.f, 0.f, 0.f, 0.f);
        if (e < r1) {
            s = g_esrc[e];
            float4 as = g_alS1[s];
            ev.x = __expf(lrelu(as.x + ad.x));
            ev.y = __expf(lrelu(as.y + ad.y));
            ev.z = __expf(lrelu(as.z + ad.z));
            ev.w = __expf(lrelu(as.w + ad.w));
            den.x += ev.x; den.y += ev.y; den.z += ev.z; den.w += ev.w;
        }
        ssrc[w][lane] = s;
        sev[w][lane] = ev;
        __syncwarp();

        int cnt = min(32, r1 - base);
#pragma unroll 4
        for (int j = 0; j < cnt; j++) {
            int sj = ssrc[w][j];                           // smem broadcast
            float sc = ((const float*)(sev[w] + j))[head]; // conflict-free
            float4 v = g_h1[sj * 32 + lane];
            accv.x += v.x * sc;
            accv.y += v.y * sc;
            accv.z += v.z * sc;
            accv.w += v.w * sc;
        }
        __syncwarp();
    }

    // Reduce denominators across the warp (per-head sums)
#pragma unroll
    for (int off = 16; off > 0; off >>= 1) {
        den.x += __shfl_xor_sync(0xFFFFFFFF, den.x, off);
        den.y += __shfl_xor_sync(0xFFFFFFFF, den.y, off);
        den.z += __shfl_xor_sync(0xFFFFFFFF, den.z, off);
        den.w += __shfl_xor_sync(0xFFFFFFFF, den.w, off);
    }

    // Self-loop (appended edge node->node)
    float4 asn = g_alS1[node];
    float4 evs;
    evs.x = __expf(lrelu(asn.x + ad.x));
    evs.y = __expf(lrelu(asn.y + ad.y));
    evs.z = __expf(lrelu(asn.z + ad.z));
    evs.w = __expf(lrelu(asn.w + ad.w));
    float eh = comp4(evs, head);
    float4 hv = g_h1[node * 32 + lane];
    accv.x += eh * hv.x;
    accv.y += eh * hv.y;
    accv.z += eh * hv.z;
    accv.w += eh * hv.w;

    float inv = 1.f / (comp4(den, head) + eh + 1e-16f);
    float4 bv = ((const float4*)b1)[lane];
    float4 o;
    o.x = accv.x * inv + bv.x;
    o.y = accv.y * inv + bv.y;
    o.z = accv.z * inv + bv.z;
    o.w = accv.w * inv + bv.w;
    // ELU
    o.x = o.x > 0.f ? o.x : expm1f(o.x);
    o.y = o.y > 0.f ? o.y : expm1f(o.y);
    o.z = o.z > 0.f ? o.z : expm1f(o.z);
    o.w = o.w > 0.f ? o.w : expm1f(o.w);
    g_out1[node * 32 + lane] = o;
}

// ---------------------------------------------------------------------------
// Fused GAT layer 2: warp per dst node, 1 head, 64 ch. Writes d_out.
// ---------------------------------------------------------------------------
__global__ __launch_bounds__(256) void gat2_kernel(const float* __restrict__ b2,
                                                   float* __restrict__ out,
                                                   int n) {
    __shared__ int ssrc[8][32];
    __shared__ float sev[8][32];

    int w = threadIdx.x >> 5;
    int lane = threadIdx.x & 31;
    int node = blockIdx.x * 8 + w;
    if (node >= n) return;

    int r0 = g_row[node];
    int r1 = g_row[node + 1];
    float ad = g_alD2[node];

    float2 accv = make_float2(0.f, 0.f);
    float den = 0.f;

    for (int base = r0; base < r1; base += 32) {
        int e = base + lane;
        int s = 0;
        float ev = 0.f;
        if (e < r1) {
            s = g_esrc[e];
            ev = __expf(lrelu(g_alS2[s] + ad));
            den += ev;
        }
        ssrc[w][lane] = s;
        sev[w][lane] = ev;
        __syncwarp();

        int cnt = min(32, r1 - base);
#pragma unroll 4
        for (int j = 0; j < cnt; j++) {
            int sj = ssrc[w][j];
            float ee = sev[w][j];
            float2 v = g_h2[sj * 32 + lane];
            accv.x += v.x * ee;
            accv.y += v.y * ee;
        }
        __syncwarp();
    }

#pragma unroll
    for (int off = 16; off > 0; off >>= 1)
        den += __shfl_xor_sync(0xFFFFFFFF, den, off);

    // Self-loop
    float eh = __expf(lrelu(g_alS2[node] + ad));
    float2 hv = g_h2[node * 32 + lane];
    accv.x += eh * hv.x;
    accv.y += eh * hv.y;

    float inv = 1.f / (den + eh + 1e-16f);
    float2 bv = ((const float2*)b2)[lane];
    float2 o;
    o.x = accv.x * inv + bv.x;
    o.y = accv.y * inv + bv.y;
    ((float2*)out)[node * 32 + lane] = o;
}

// ---------------------------------------------------------------------------
// Launch
// ---------------------------------------------------------------------------
extern "C" void kernel_launch(void* const* d_in, const int* in_sizes, int n_in,
                              void* d_out, int out_size) {
    const float* x   = (const float*)d_in[0];
    const void*  ei  = d_in[1];
    const float* W1  = (const float*)d_in[2];
    const float* aS1 = (const float*)d_in[3];
    const float* aD1 = (const float*)d_in[4];
    const float* b1  = (const float*)d_in[5];
    const float* W2  = (const float*)d_in[6];
    const float* aS2 = (const float*)d_in[7];
    const float* aD2 = (const float*)d_in[8];
    const float* b2  = (const float*)d_in[9];
    float* out       = (float*)d_out;

    const int n = in_sizes[0] / 128;
    const int E = in_sizes[1] / 2;

    const int gemm_blocks = (n + 63) / 64;
    const int node_blocks = (n + 7) / 8;        // warp per node
    const int edge_blocks = (E + 255) / 256;
    const int scan_blocks = (n + SCAN_CHUNK - 1) / SCAN_CHUNK;

    // Edge dtype probe + CSR build (shared by both layers)
    probe_kernel<<<1, 256>>>(ei, n);
    zero_deg_kernel<<<(n + 255) / 256, 256>>>(n);
    hist_kernel<<<edge_blocks, 256>>>(ei, E, n);
    scanA_kernel<<<scan_blocks, SCAN_T>>>(n);
    scanB_kernel<<<1, 32>>>(scan_blocks, n);
    scanC_kernel<<<scan_blocks, SCAN_T>>>(n);
    permute_kernel<<<edge_blocks, 256>>>(ei, E, n);

    // Layer 1
    gemm_kernel<1><<<gemm_blocks, 256>>>(x, W1, aS1, aD1, n);
    gat1_kernel<<<node_blocks, 256>>>(b1, n);

    // Layer 2
    gemm_kernel<2><<<gemm_blocks, 256>>>(nullptr, W2, aS2, aD2, n);
    gat2_kernel<<<node_blocks, 256>>>(b2, out, n);
}

// round 9
// speedup vs baseline: 1.5141x; 1.0349x over previous
#include <cuda_runtime.h>
#include <cuda_fp16.h>
#include <math.h>

// Problem constants (fixed by the reference)
#define NMAX 50000
#define EMAX 1600000
#define NEG_SLOPE 0.2f

#define SCAN_T 256
#define SCAN_I 8
#define SCAN_CHUNK (SCAN_T * SCAN_I)   // 2048 elements per block
#define SCAN_MAXB ((NMAX + SCAN_CHUNK - 1) / SCAN_CHUNK + 1)

// ---------------------------------------------------------------------------
// Scratch (static __device__ globals; runtime alloc is forbidden)
// ---------------------------------------------------------------------------
__device__ __half2 g_h1h[NMAX * 64];  // [N,128] layer-1 features, fp16
__device__ float4  g_out1[NMAX * 32]; // [N,128] layer-1 output (post ELU), fp32
__device__ float4  g_alS1[NMAX];      // [N,4] attention logits (src)
__device__ float4  g_alD1[NMAX];      // [N,4] attention logits (dst)

__device__ __half2 g_h2h[NMAX * 32];  // [N,64] layer-2 features, fp16
__device__ float   g_alS2[NMAX];
__device__ float   g_alD2[NMAX];

__device__ int     g_is64;            // edge_index dtype flag (1 = int64)
__device__ int     g_deg[NMAX];       // dst-degree histogram
__device__ int     g_row[NMAX + 1];   // CSR row offsets (by dst)
__device__ int     g_cursor[NMAX];    // scatter cursors
__device__ int     g_esrc[EMAX];      // src ids sorted by dst
__device__ int     g_bsum[SCAN_MAXB]; // per-block degree sums
__device__ int     g_boff[SCAN_MAXB]; // per-block exclusive offsets

// ---------------------------------------------------------------------------
// Helpers
// ---------------------------------------------------------------------------
__device__ __forceinline__ float lrelu(float x) {
    return x > 0.f ? x : NEG_SLOPE * x;
}
__device__ __forceinline__ float comp4(float4 v, int i) {
    return i == 0 ? v.x : (i == 1 ? v.y : (i == 2 ? v.z : v.w));
}

// ---------------------------------------------------------------------------
// Probe (parallel): decide whether edge_index is int64 or int32.
// ---------------------------------------------------------------------------
__global__ void probe_kernel(const void* ei, int n) {
    __shared__ int bad;
    if (threadIdx.x == 0) bad = 0;
    __syncthreads();
    const long long* p = (const long long*)ei;
    long long v = p[threadIdx.x];
    if (v < 0 || v >= n) atomicOr(&bad, 1);
    __syncthreads();
    if (threadIdx.x == 0) g_is64 = bad ? 0 : 1;
}

// ---------------------------------------------------------------------------
// CSR build: zero -> histogram -> 3-phase scan -> permute
// ---------------------------------------------------------------------------
__global__ void zero_deg_kernel(int n) {
    int i = blockIdx.x * blockDim.x + threadIdx.x;
    if (i < n) g_deg[i] = 0;
}

__global__ void hist_kernel(const void* __restrict__ ei, int E, int n) {
    int e = blockIdx.x * blockDim.x + threadIdx.x;
    if (e >= E) return;
    int d;
    if (g_is64) d = (int)((const long long*)ei)[E + e];
    else        d = ((const int*)ei)[E + e];
    d = min(max(d, 0), n - 1);
    atomicAdd(&g_deg[d], 1);
}

// Phase A: per-block sum of 2048 degrees.
__global__ __launch_bounds__(SCAN_T) void scanA_kernel(int n) {
    __shared__ int sm[SCAN_T];
    int t = threadIdx.x;
    int base = blockIdx.x * SCAN_CHUNK + t * SCAN_I;
    int s = 0;
#pragma unroll
    for (int i = 0; i < SCAN_I; i++) {
        int idx = base + i;
        if (idx < n) s += g_deg[idx];
    }
    sm[t] = s;
    __syncthreads();
#pragma unroll
    for (int off = SCAN_T / 2; off > 0; off >>= 1) {
        if (t < off) sm[t] += sm[t + off];
        __syncthreads();
    }
    if (t == 0) g_bsum[blockIdx.x] = sm[0];
}

// Phase B: serial exclusive scan over <=25 block sums (tiny).
__global__ void scanB_kernel(int nb, int n) {
    if (threadIdx.x != 0) return;
    int acc = 0;
    for (int i = 0; i < nb; i++) {
        g_boff[i] = acc;
        acc += g_bsum[i];
    }
    g_row[n] = acc;
}

// Phase C: per-block exclusive scan with global offset; writes row + cursor.
__global__ __launch_bounds__(SCAN_T) void scanC_kernel(int n) {
    __shared__ int sm[SCAN_T];
    int t = threadIdx.x;
    int base = blockIdx.x * SCAN_CHUNK + t * SCAN_I;
    int loc[SCAN_I];
    int s = 0;
#pragma unroll
    for (int i = 0; i < SCAN_I; i++) {
        int idx = base + i;
        loc[i] = (idx < n) ? g_deg[idx] : 0;
        s += loc[i];
    }
    sm[t] = s;
    __syncthreads();
#pragma unroll
    for (int off = 1; off < SCAN_T; off <<= 1) {
        int v = (t >= off) ? sm[t - off] : 0;
        __syncthreads();
        sm[t] += v;
        __syncthreads();
    }
    int acc = ((t == 0) ? 0 : sm[t - 1]) + g_boff[blockIdx.x];
#pragma unroll
    for (int i = 0; i < SCAN_I; i++) {
        int idx = base + i;
        if (idx < n) {
            g_row[idx] = acc;
            g_cursor[idx] = acc;
            acc += loc[i];
        }
    }
}

__global__ void permute_kernel(const void* __restrict__ ei, int E, int n) {
    int e = blockIdx.x * blockDim.x + threadIdx.x;
    if (e >= E) return;
    int s, d;
    if (g_is64) {
        s = (int)((const long long*)ei)[e];
        d = (int)((const long long*)ei)[E + e];
    } else {
        s = ((const int*)ei)[e];
        d = ((const int*)ei)[E + e];
    }
    s = min(max(s, 0), n - 1);
    d = min(max(d, 0), n - 1);
    int pos = atomicAdd(&g_cursor[d], 1);
    if (pos < EMAX) g_esrc[pos] = s;
}

// ---------------------------------------------------------------------------
// GEMM with fused attention-logit epilogue.
// H[M, NC] = X[M, 128] @ W[128, NC]; logits from fp32 accumulators,
// features stored to fp16 (__half2) for the gather-heavy GAT pass.
// ---------------------------------------------------------------------------
template <int LAYER>
__global__ __launch_bounds__(256) void gemm_kernel(const float* __restrict__ Xin,
                                                   const float* __restrict__ W,
                                                   const float* __restrict__ aS,
                                                   const float* __restrict__ aD,
                                                   int M) {
    constexpr int NC = (LAYER == 1) ? 128 : 64;
    constexpr int TN = NC / 16;
    const float* __restrict__ X = (LAYER == 1) ? Xin : (const float*)g_out1;
    __half2* __restrict__ Hh = (LAYER == 1) ? g_h1h : g_h2h;

    __shared__ __align__(16) float Xs[64][32];
    __shared__ __align__(16) float Ws[32][NC];

    const int t = threadIdx.x;
    const int row0 = blockIdx.x * 64;
    const int tr = t >> 4;        // 0..15
    const int tc = t & 15;        // 0..15

    float acc[4][TN];
#pragma unroll
    for (int i = 0; i < 4; i++)
#pragma unroll
        for (int j = 0; j < TN; j++) acc[i][j] = 0.f;

    for (int kk = 0; kk < 128; kk += 32) {
#pragma unroll
        for (int i = 0; i < 8; i++) {
            int idx = i * 256 + t;
            int r = idx >> 5, c = idx & 31;
            int gr = row0 + r;
            Xs[r][c] = (gr < M) ? X[gr * 128 + kk + c] : 0.f;
        }
#pragma unroll
        for (int i = 0; i < NC / 8; i++) {
            int idx = i * 256 + t;
            int r = idx / NC, c = idx % NC;
            Ws[r][c] = W[(kk + r) * NC + c];
        }
        __syncthreads();

#pragma unroll
        for (int k = 0; k < 32; k++) {
            float xv[4];
#pragma unroll
            for (int i = 0; i < 4; i++) xv[i] = Xs[tr + 16 * i][k];
            float wv[TN];
            const float4* wrow = (const float4*)&Ws[k][0];
#pragma unroll
            for (int j4 = 0; j4 < TN / 4; j4++) {
                float4 w = wrow[tc * (TN / 4) + j4];
                wv[j4 * 4 + 0] = w.x; wv[j4 * 4 + 1] = w.y;
                wv[j4 * 4 + 2] = w.z; wv[j4 * 4 + 3] = w.w;
            }
#pragma unroll
            for (int i = 0; i < 4; i++)
#pragma unroll
                for (int j = 0; j < TN; j++) acc[i][j] += xv[i] * wv[j];
        }
        __syncthreads();
    }

    // Store H as fp16 (__half2 pairs)
#pragma unroll
    for (int i = 0; i < 4; i++) {
        int gr = row0 + tr + 16 * i;
        if (gr < M) {
#pragma unroll
            for (int j2 = 0; j2 < TN / 2; j2++) {
                Hh[gr * (NC / 2) + tc * (TN / 2) + j2] =
                    __floats2half2_rn(acc[i][j2 * 2], acc[i][j2 * 2 + 1]);
            }
        }
    }

    // Fused logits (from fp32 accumulators)
    if (LAYER == 1) {
        int head = tc >> 2;
        int sub = tc & 3;
        float av[8], dv[8];
#pragma unroll
        for (int j = 0; j < 8; j++) {
            av[j] = aS[head * 32 + sub * 8 + j];
            dv[j] = aD[head * 32 + sub * 8 + j];
        }
#pragma unroll
        for (int i = 0; i < 4; i++) {
            float ps = 0.f, pd = 0.f;
#pragma unroll
            for (int j = 0; j < 8; j++) {
                ps += acc[i][j] * av[j];
                pd += acc[i][j] * dv[j];
            }
            ps += __shfl_xor_sync(0xFFFFFFFF, ps, 1);
            ps += __shfl_xor_sync(0xFFFFFFFF, ps, 2);
            pd += __shfl_xor_sync(0xFFFFFFFF, pd, 1);
            pd += __shfl_xor_sync(0xFFFFFFFF, pd, 2);
            int gr = row0 + tr + 16 * i;
            if (sub == 0 && gr < M) {
                ((float*)g_alS1)[gr * 4 + head] = ps;
                ((float*)g_alD1)[gr * 4 + head] = pd;
            }
        }
    } else {
        float av[4], dv[4];
#pragma unroll
        for (int j = 0; j < 4; j++) {
            av[j] = aS[tc * 4 + j];
            dv[j] = aD[tc * 4 + j];
        }
#pragma unroll
        for (int i = 0; i < 4; i++) {
            float ps = 0.f, pd = 0.f;
#pragma unroll
            for (int j = 0; j < 4; j++) {
                ps += acc[i][j] * av[j];
                pd += acc[i][j] * dv[j];
            }
#pragma unroll
            for (int off = 1; off < 16; off <<= 1) {
                ps += __shfl_xor_sync(0xFFFFFFFF, ps, off);
                pd += __shfl_xor_sync(0xFFFFFFFF, pd, off);
            }
            int gr = row0 + tr + 16 * i;
            if (tc == 0 && gr < M) {
                g_alS2[gr] = ps;
                g_alD2[gr] = pd;
            }
        }
    }
}

// ---------------------------------------------------------------------------
// Fused GAT layer 1: warp per dst node. Walk CSR row, gather fp16 h1[src]
// (8B per lane per edge), accumulate in fp32 registers, fold self-loop,
// normalize, add bias, ELU, write g_out1 fp32. No atomics.
// ---------------------------------------------------------------------------
__global__ __launch_bounds__(256) void gat1_kernel(const float* __restrict__ b1,
                                                   int n) {
    __shared__ int ssrc[8][32];
    __shared__ float4 sev[8][32];

    int w = threadIdx.x >> 5;
    int lane = threadIdx.x & 31;
    int node = blockIdx.x * 8 + w;
    if (node >= n) return;
    int head = lane >> 3;

    int r0 = g_row[node];
    int r1 = g_row[node + 1];
    float4 ad = g_alD1[node];

    float4 accv = make_float4(0.f, 0.f, 0.f, 0.f);
    float4 den = make_float4(0.f, 0.f, 0.f, 0.f);

    for (int base = r0; base < r1; base += 32) {
        int e = base + lane;
        int s = 0;
        float4 ev = make_float4(0.f, 0.f, 0.f, 0.f);
        if (e < r1) {
            s = g_esrc[e];
            float4 as = g_alS1[s];
            ev.x = __expf(lrelu(as.x + ad.x));
            ev.y = __expf(lrelu(as.y + ad.y));
            ev.z = __expf(lrelu(as.z + ad.z));
            ev.w = __expf(lrelu(as.w + ad.w));
            den.x += ev.x; den.y += ev.y; den.z += ev.z; den.w += ev.w;
        }
        ssrc[w][lane] = s;
        sev[w][lane] = ev;
        __syncwarp();

        int cnt = min(32, r1 - base);
#pragma unroll 4
        for (int j = 0; j < cnt; j++) {
            int sj = ssrc[w][j];                           // smem broadcast
            float sc = ((const float*)(sev[w] + j))[head]; // conflict-free
            // 8B load: 2 half2 = 4 channels
            uint2 raw = *reinterpret_cast<const uint2*>(&g_h1h[sj * 64 + lane * 2]);
            float2 va = __half22float2(*reinterpret_cast<__half2*>(&raw.x));
            float2 vb = __half22float2(*reinterpret_cast<__half2*>(&raw.y));
            accv.x += va.x * sc;
            accv.y += va.y * sc;
            accv.z += vb.x * sc;
            accv.w += vb.y * sc;
        }
        __syncwarp();
    }

    // Reduce denominators across the warp (per-head sums)
#pragma unroll
    for (int off = 16; off > 0; off >>= 1) {
        den.x += __shfl_xor_sync(0xFFFFFFFF, den.x, off);
        den.y += __shfl_xor_sync(0xFFFFFFFF, den.y, off);
        den.z += __shfl_xor_sync(0xFFFFFFFF, den.z, off);
        den.w += __shfl_xor_sync(0xFFFFFFFF, den.w, off);
    }

    // Self-loop (appended edge node->node)
    float4 asn = g_alS1[node];
    float4 evs;
    evs.x = __expf(lrelu(asn.x + ad.x));
    evs.y = __expf(lrelu(asn.y + ad.y));
    evs.z = __expf(lrelu(asn.z + ad.z));
    evs.w = __expf(lrelu(asn.w + ad.w));
    float eh = comp4(evs, head);
    {
        uint2 raw = *reinterpret_cast<const uint2*>(&g_h1h[node * 64 + lane * 2]);
        float2 va = __half22float2(*reinterpret_cast<__half2*>(&raw.x));
        float2 vb = __half22float2(*reinterpret_cast<__half2*>(&raw.y));
        accv.x += eh * va.x;
        accv.y += eh * va.y;
        accv.z += eh * vb.x;
        accv.w += eh * vb.y;
    }

    float inv = 1.f / (comp4(den, head) + eh + 1e-16f);
    float4 bv = ((const float4*)b1)[lane];
    float4 o;
    o.x = accv.x * inv + bv.x;
    o.y = accv.y * inv + bv.y;
    o.z = accv.z * inv + bv.z;
    o.w = accv.w * inv + bv.w;
    // ELU
    o.x = o.x > 0.f ? o.x : expm1f(o.x);
    o.y = o.y > 0.f ? o.y : expm1f(o.y);
    o.z = o.z > 0.f ? o.z : expm1f(o.z);
    o.w = o.w > 0.f ? o.w : expm1f(o.w);
    g_out1[node * 32 + lane] = o;
}

// ---------------------------------------------------------------------------
// Fused GAT layer 2: warp per dst node, 1 head, 64 ch fp16. Writes d_out fp32.
// ---------------------------------------------------------------------------
__global__ __launch_bounds__(256) void gat2_kernel(const float* __restrict__ b2,
                                                   float* __restrict__ out,
                                                   int n) {
    __shared__ int ssrc[8][32];
    __shared__ float sev[8][32];

    int w = threadIdx.x >> 5;
    int lane = threadIdx.x & 31;
    int node = blockIdx.x * 8 + w;
    if (node >= n) return;

    int r0 = g_row[node];
    int r1 = g_row[node + 1];
    float ad = g_alD2[node];

    float2 accv = make_float2(0.f, 0.f);
    float den = 0.f;

    for (int base = r0; base < r1; base += 32) {
        int e = base + lane;
        int s = 0;
        float ev = 0.f;
        if (e < r1) {
            s = g_esrc[e];
            ev = __expf(lrelu(g_alS2[s] + ad));
            den += ev;
        }
        ssrc[w][lane] = s;
        sev[w][lane] = ev;
        __syncwarp();

        int cnt = min(32, r1 - base);
#pragma unroll 4
        for (int j = 0; j < cnt; j++) {
            int sj = ssrc[w][j];
            float ee = sev[w][j];
            float2 v = __half22float2(g_h2h[sj * 32 + lane]);
            accv.x += v.x * ee;
            accv.y += v.y * ee;
        }
        __syncwarp();
    }

#pragma unroll
    for (int off = 16; off > 0; off >>= 1)
        den += __shfl_xor_sync(0xFFFFFFFF, den, off);

    // Self-loop
    float eh = __expf(lrelu(g_alS2[node] + ad));
    float2 hv = __half22float2(g_h2h[node * 32 + lane]);
    accv.x += eh * hv.x;
    accv.y += eh * hv.y;

    float inv = 1.f / (den + eh + 1e-16f);
    float2 bv = ((const float2*)b2)[lane];
    float2 o;
    o.x = accv.x * inv + bv.x;
    o.y = accv.y * inv + bv.y;
    ((float2*)out)[node * 32 + lane] = o;
}

// ---------------------------------------------------------------------------
// Launch
// ---------------------------------------------------------------------------
extern "C" void kernel_launch(void* const* d_in, const int* in_sizes, int n_in,
                              void* d_out, int out_size) {
    const float* x   = (const float*)d_in[0];
    const void*  ei  = d_in[1];
    const float* W1  = (const float*)d_in[2];
    const float* aS1 = (const float*)d_in[3];
    const float* aD1 = (const float*)d_in[4];
    const float* b1  = (const float*)d_in[5];
    const float* W2  = (const float*)d_in[6];
    const float* aS2 = (const float*)d_in[7];
    const float* aD2 = (const float*)d_in[8];
    const float* b2  = (const float*)d_in[9];
    float* out       = (float*)d_out;

    const int n = in_sizes[0] / 128;
    const int E = in_sizes[1] / 2;

    const int gemm_blocks = (n + 63) / 64;
    const int node_blocks = (n + 7) / 8;        // warp per node
    const int edge_blocks = (E + 255) / 256;
    const int scan_blocks = (n + SCAN_CHUNK - 1) / SCAN_CHUNK;

    // Edge dtype probe + CSR build (shared by both layers)
    probe_kernel<<<1, 256>>>(ei, n);
    zero_deg_kernel<<<(n + 255) / 256, 256>>>(n);
    hist_kernel<<<edge_blocks, 256>>>(ei, E, n);
    scanA_kernel<<<scan_blocks, SCAN_T>>>(n);
    scanB_kernel<<<1, 32>>>(scan_blocks, n);
    scanC_kernel<<<scan_blocks, SCAN_T>>>(n);
    permute_kernel<<<edge_blocks, 256>>>(ei, E, n);

    // Layer 1
    gemm_kernel<1><<<gemm_blocks, 256>>>(x, W1, aS1, aD1, n);
    gat1_kernel<<<node_blocks, 256>>>(b1, n);

    // Layer 2
    gemm_kernel<2><<<gemm_blocks, 256>>>(nullptr, W2, aS2, aD2, n);
    gat2_kernel<<<node_blocks, 256>>>(b2, out, n);
}